// round 4
// baseline (speedup 1.0000x reference)
#include <cuda_runtime.h>

#define BB 8
#define SS 2048
#define EE 1024
#define HH 128

// Scratch for Q/K/V projections (8 MB each) — __device__ globals per harness rules.
__device__ float g_q[BB * SS * HH];
__device__ float g_k[BB * SS * HH];
__device__ float g_v[BB * SS * HH];

// ---------------------------------------------------------------------------
// Kernel 1: QKV projection.  C[16384,128] = X[16384,1024] @ W[1024,128]
// blockIdx.x: 64-row tile of X; blockIdx.y in {0,1,2} selects (wq,wk,wv).
// 256 threads; each computes a 4x8 micro-tile.
// ---------------------------------------------------------------------------
__global__ __launch_bounds__(256) void proj_kernel(
    const float* __restrict__ x, const float* __restrict__ wq,
    const float* __restrict__ wk, const float* __restrict__ wv)
{
    __shared__ float Xs[64][32];
    __shared__ float Ws[32][128];

    const int which = blockIdx.y;
    const float* __restrict__ w = (which == 0) ? wq : (which == 1) ? wk : wv;
    float* __restrict__ out = (which == 0) ? g_q : (which == 1) ? g_k : g_v;

    const int row0 = blockIdx.x * 64;
    const int tid = threadIdx.x;
    const int tx = tid & 15;   // 16 column groups of 8
    const int ty = tid >> 4;   // 16 row groups of 4

    float acc[4][8];
#pragma unroll
    for (int i = 0; i < 4; i++)
#pragma unroll
        for (int j = 0; j < 8; j++) acc[i][j] = 0.0f;

    for (int k0 = 0; k0 < EE; k0 += 32) {
        // Load X tile: 64x32 floats, 2 float4 per thread.
#pragma unroll
        for (int i = 0; i < 2; i++) {
            int idx = (tid + i * 256) * 4;
            int r = idx >> 5, c = idx & 31;
            *(float4*)&Xs[r][c] =
                *(const float4*)&x[(size_t)(row0 + r) * EE + k0 + c];
        }
        // Load W tile: 32x128 floats, 4 float4 per thread.
#pragma unroll
        for (int i = 0; i < 4; i++) {
            int idx = (tid + i * 256) * 4;
            int r = idx >> 7, c = idx & 127;
            *(float4*)&Ws[r][c] =
                *(const float4*)&w[(size_t)(k0 + r) * HH + c];
        }
        __syncthreads();

#pragma unroll
        for (int kk = 0; kk < 32; kk++) {
            float xv[4];
#pragma unroll
            for (int i = 0; i < 4; i++) xv[i] = Xs[ty * 4 + i][kk];
            float4 wa = *(const float4*)&Ws[kk][tx * 8];
            float4 wb = *(const float4*)&Ws[kk][tx * 8 + 4];
            float wv8[8] = {wa.x, wa.y, wa.z, wa.w, wb.x, wb.y, wb.z, wb.w};
#pragma unroll
            for (int i = 0; i < 4; i++)
#pragma unroll
                for (int j = 0; j < 8; j++) acc[i][j] += xv[i] * wv8[j];
        }
        __syncthreads();
    }

#pragma unroll
    for (int i = 0; i < 4; i++) {
        size_t o = (size_t)(row0 + ty * 4 + i) * HH + tx * 8;
        *(float4*)&out[o]     = make_float4(acc[i][0], acc[i][1], acc[i][2], acc[i][3]);
        *(float4*)&out[o + 4] = make_float4(acc[i][4], acc[i][5], acc[i][6], acc[i][7]);
    }
}

// ---------------------------------------------------------------------------
// Kernel 2: flash attention with dropout folded into the numerator.
// Block = (batch b, 64-row Q tile). 256 threads.
// QK phase: thread (ty,tx) owns rows ty*4..+3, cols tx*4..+3 of the 64x64 S tile.
// PV phase: same rows, head cols tx*8..+7. Row ownership identical -> m/l/alpha
// stay in registers, no cross-thread handoff.
// Dynamic smem: Qs/Ks/Vs padded [64][132], Ps [64][68].
// ---------------------------------------------------------------------------
#define QKV_PITCH 132
#define P_PITCH 68
#define ATTN_SMEM_FLOATS (3 * 64 * QKV_PITCH + 64 * P_PITCH)
#define ATTN_SMEM_BYTES (ATTN_SMEM_FLOATS * 4)

__global__ __launch_bounds__(256) void attn_kernel(
    const float* __restrict__ drop_u, float* __restrict__ out)
{
    extern __shared__ float smem[];
    float* Qs = smem;                      // [64][132]
    float* Ks = Qs + 64 * QKV_PITCH;       // [64][132]
    float* Vs = Ks + 64 * QKV_PITCH;       // [64][132]
    float* Ps = Vs + 64 * QKV_PITCH;       // [64][68]

    const int b = blockIdx.y;
    const int q0 = blockIdx.x * 64;
    const int tid = threadIdx.x;
    const int tx = tid & 15;
    const int ty = tid >> 4;

    const float* __restrict__ qg = g_q + (size_t)b * SS * HH;
    const float* __restrict__ kg = g_k + (size_t)b * SS * HH;
    const float* __restrict__ vg = g_v + (size_t)b * SS * HH;
    const float* __restrict__ du = drop_u + (size_t)b * SS * SS;

    // Load Q tile once: 64x128 floats, 8 float4 per thread.
#pragma unroll
    for (int i = 0; i < 8; i++) {
        int idx = (tid + i * 256) * 4;
        int r = idx >> 7, c = idx & 127;
        *(float4*)&Qs[r * QKV_PITCH + c] =
            *(const float4*)&qg[(size_t)(q0 + r) * HH + c];
    }

    float m[4], l[4], o[4][8];
#pragma unroll
    for (int i = 0; i < 4; i++) {
        m[i] = -1e30f;
        l[i] = 0.0f;
#pragma unroll
        for (int j = 0; j < 8; j++) o[i][j] = 0.0f;
    }

    const float scale = 0.03125f;          // 1024^-0.5
    const float inv_keep = 1.0f / 0.9f;

    for (int k0 = 0; k0 < SS; k0 += 64) {
        __syncthreads();   // previous PV reads of Ks/Vs done
        // Load K and V tiles.
#pragma unroll
        for (int i = 0; i < 8; i++) {
            int idx = (tid + i * 256) * 4;
            int r = idx >> 7, c = idx & 127;
            *(float4*)&Ks[r * QKV_PITCH + c] =
                *(const float4*)&kg[(size_t)(k0 + r) * HH + c];
            *(float4*)&Vs[r * QKV_PITCH + c] =
                *(const float4*)&vg[(size_t)(k0 + r) * HH + c];
        }
        // Prefetch dropout tile entries owned by this thread (overlaps with QK).
        float4 dr[4];
#pragma unroll
        for (int i = 0; i < 4; i++)
            dr[i] = *(const float4*)&du[(size_t)(q0 + ty * 4 + i) * SS + k0 + tx * 4];
        __syncthreads();

        // ---- S = scale * Q K^T  (4x4 per thread) ----
        float s[4][4];
#pragma unroll
        for (int i = 0; i < 4; i++)
#pragma unroll
            for (int j = 0; j < 4; j++) s[i][j] = 0.0f;

#pragma unroll
        for (int h = 0; h < HH; h += 4) {
            float4 qv[4], kv[4];
#pragma unroll
            for (int i = 0; i < 4; i++)
                qv[i] = *(const float4*)&Qs[(ty * 4 + i) * QKV_PITCH + h];
#pragma unroll
            for (int j = 0; j < 4; j++)
                kv[j] = *(const float4*)&Ks[(tx * 4 + j) * QKV_PITCH + h];
#pragma unroll
            for (int i = 0; i < 4; i++)
#pragma unroll
                for (int j = 0; j < 4; j++) {
                    s[i][j] += qv[i].x * kv[j].x;
                    s[i][j] += qv[i].y * kv[j].y;
                    s[i][j] += qv[i].z * kv[j].z;
                    s[i][j] += qv[i].w * kv[j].w;
                }
        }

        // ---- online softmax (+ dropout into numerator only) ----
        float alpha[4];
#pragma unroll
        for (int i = 0; i < 4; i++) {
            float p0 = s[i][0] * scale, p1 = s[i][1] * scale;
            float p2 = s[i][2] * scale, p3 = s[i][3] * scale;
            float mt = fmaxf(fmaxf(p0, p1), fmaxf(p2, p3));
#pragma unroll
            for (int off = 8; off > 0; off >>= 1)
                mt = fmaxf(mt, __shfl_xor_sync(0xffffffffu, mt, off));
            float mn = fmaxf(m[i], mt);
            p0 = __expf(p0 - mn); p1 = __expf(p1 - mn);
            p2 = __expf(p2 - mn); p3 = __expf(p3 - mn);
            float sum = p0 + p1 + p2 + p3;
#pragma unroll
            for (int off = 8; off > 0; off >>= 1)
                sum += __shfl_xor_sync(0xffffffffu, sum, off);
            alpha[i] = __expf(m[i] - mn);
            l[i] = l[i] * alpha[i] + sum;   // denominator WITHOUT dropout
            m[i] = mn;
            // dropout applied only to numerator P
            p0 *= (dr[i].x >= 0.1f) ? inv_keep : 0.0f;
            p1 *= (dr[i].y >= 0.1f) ? inv_keep : 0.0f;
            p2 *= (dr[i].z >= 0.1f) ? inv_keep : 0.0f;
            p3 *= (dr[i].w >= 0.1f) ? inv_keep : 0.0f;
            *(float4*)&Ps[(ty * 4 + i) * P_PITCH + tx * 4] =
                make_float4(p0, p1, p2, p3);
        }
        __syncthreads();

        // ---- O = O*alpha + P V  (4 rows x 8 head cols per thread) ----
#pragma unroll
        for (int i = 0; i < 4; i++)
#pragma unroll
            for (int j = 0; j < 8; j++) o[i][j] *= alpha[i];

#pragma unroll 4
        for (int c = 0; c < 64; c++) {
            float pv[4];
#pragma unroll
            for (int i = 0; i < 4; i++) pv[i] = Ps[(ty * 4 + i) * P_PITCH + c];
            float4 va = *(const float4*)&Vs[c * QKV_PITCH + tx * 8];
            float4 vb = *(const float4*)&Vs[c * QKV_PITCH + tx * 8 + 4];
#pragma unroll
            for (int i = 0; i < 4; i++) {
                o[i][0] += pv[i] * va.x;
                o[i][1] += pv[i] * va.y;
                o[i][2] += pv[i] * va.z;
                o[i][3] += pv[i] * va.w;
                o[i][4] += pv[i] * vb.x;
                o[i][5] += pv[i] * vb.y;
                o[i][6] += pv[i] * vb.z;
                o[i][7] += pv[i] * vb.w;
            }
        }
    }

    // epilogue: divide by softmax denominator, store
#pragma unroll
    for (int i = 0; i < 4; i++) {
        float inv = 1.0f / l[i];
        size_t oidx = (size_t)b * SS * HH + (size_t)(q0 + ty * 4 + i) * HH + tx * 8;
        *(float4*)&out[oidx] =
            make_float4(o[i][0] * inv, o[i][1] * inv, o[i][2] * inv, o[i][3] * inv);
        *(float4*)&out[oidx + 4] =
            make_float4(o[i][4] * inv, o[i][5] * inv, o[i][6] * inv, o[i][7] * inv);
    }
}

extern "C" void kernel_launch(void* const* d_in, const int* in_sizes, int n_in,
                              void* d_out, int out_size)
{
    const float* x  = (const float*)d_in[0];
    const float* wq = (const float*)d_in[1];
    const float* wk = (const float*)d_in[2];
    const float* wv = (const float*)d_in[3];
    const float* du = (const float*)d_in[4];
    float* out = (float*)d_out;

    cudaFuncSetAttribute(attn_kernel,
                         cudaFuncAttributeMaxDynamicSharedMemorySize,
                         ATTN_SMEM_BYTES);

    dim3 g1(BB * SS / 64, 3);
    proj_kernel<<<g1, 256>>>(x, wq, wk, wv);

    dim3 g2(SS / 64, BB);
    attn_kernel<<<g2, 256, ATTN_SMEM_BYTES>>>(du, out);
}

// round 6
// speedup vs baseline: 4.0167x; 4.0167x over previous
#include <cuda_runtime.h>
#include <cuda_bf16.h>

#define BB 8
#define SS 2048
#define EE 1024
#define HH 128

typedef unsigned int u32;

// ---------------- device scratch ----------------
__device__ __nv_bfloat16 g_xh[BB*SS*EE], g_xl[BB*SS*EE];     // X split [s][e]
__device__ __nv_bfloat16 g_wth[3][HH*EE], g_wtl[3][HH*EE];   // W^T split [h][e]
__device__ __nv_bfloat16 g_qh[BB*SS*HH], g_ql[BB*SS*HH];     // Q [s][h]
__device__ __nv_bfloat16 g_kh[BB*SS*HH], g_kl[BB*SS*HH];     // K [s][h]
__device__ __nv_bfloat16 g_vth[BB*HH*SS], g_vtl[BB*HH*SS];   // V^T [b][h][s]

// ---------------- helpers ----------------
__device__ __forceinline__ u32 smem_u32(const void* p) {
    u32 a;
    asm("{ .reg .u64 t; cvta.to.shared.u64 t, %1; cvt.u32.u64 %0, t; }" : "=r"(a) : "l"(p));
    return a;
}
__device__ __forceinline__ void cpa16(u32 dst, const void* src) {
    asm volatile("cp.async.cg.shared.global [%0], [%1], 16;" :: "r"(dst), "l"(src));
}
#define CP_COMMIT() asm volatile("cp.async.commit_group;" ::: "memory")
#define CP_WAIT(n)  asm volatile("cp.async.wait_group %0;" :: "n"(n) : "memory")

// pack two f32 -> bf16x2 (low lane = first arg)
__device__ __forceinline__ u32 packbf(float lo, float hi) {
    u32 r;
    asm("cvt.rn.bf16x2.f32 %0, %1, %2;" : "=r"(r) : "f"(hi), "f"(lo));
    return r;
}
// residual (lo part) of split given packed hi
__device__ __forceinline__ u32 packlo(float p0, float p1, u32 h) {
    float r0 = p0 - __uint_as_float(h << 16);
    float r1 = p1 - __uint_as_float(h & 0xffff0000u);
    return packbf(r0, r1);
}
__device__ __forceinline__ void mma16816(float* c, u32 a0, u32 a1, u32 a2, u32 a3,
                                         u32 b0, u32 b1) {
    asm volatile("mma.sync.aligned.m16n8k16.row.col.f32.bf16.bf16.f32 "
                 "{%0,%1,%2,%3},{%4,%5,%6,%7},{%8,%9},{%0,%1,%2,%3};"
                 : "+f"(c[0]), "+f"(c[1]), "+f"(c[2]), "+f"(c[3])
                 : "r"(a0), "r"(a1), "r"(a2), "r"(a3), "r"(b0), "r"(b1));
}

// ---------------------------------------------------------------------------
// prep: X f32 -> hi/lo bf16 (same layout); W [e][h] f32 -> W^T [h][e] hi/lo
// ---------------------------------------------------------------------------
__global__ __launch_bounds__(256) void xprep_kernel(const float* __restrict__ x) {
    size_t i = ((size_t)blockIdx.x * 256 + threadIdx.x) * 4;
    float4 v = *(const float4*)(x + i);
    u32 h01 = packbf(v.x, v.y), h23 = packbf(v.z, v.w);
    u32 l01 = packlo(v.x, v.y, h01), l23 = packlo(v.z, v.w, h23);
    *(uint2*)&g_xh[i] = make_uint2(h01, h23);
    *(uint2*)&g_xl[i] = make_uint2(l01, l23);
}
__global__ __launch_bounds__(256) void wprep_kernel(
    const float* __restrict__ wq, const float* __restrict__ wk,
    const float* __restrict__ wv)
{
    int idx = blockIdx.x * 256 + threadIdx.x;   // e*128+h
    int e = idx >> 7, h = idx & 127;
    int o = h * EE + e;
    const float* src[3] = {wq, wk, wv};
#pragma unroll
    for (int m = 0; m < 3; m++) {
        float v = src[m][idx];
        __nv_bfloat16 hi = __float2bfloat16_rn(v);
        g_wth[m][o] = hi;
        g_wtl[m][o] = __float2bfloat16_rn(v - __bfloat162float(hi));
    }
}

// ---------------------------------------------------------------------------
// proj: C[128rows x 128h] = X @ W  (one of q/k/v per blockIdx.y), HMMA 3-pass,
// cp.async double-buffered over 16 k-chunks of 64.
// smem tile: [128][72] bf16 (pad 8 -> 144B rows, conflict-free frag loads).
// ---------------------------------------------------------------------------
#define PJ_T 18432            // 128*72*2
#define PJ_STG (4 * PJ_T)     // Xh,Xl,Wh,Wl per stage
#define PROJ_SMEM (2 * PJ_STG)

__device__ __forceinline__ void chunk_load(u32 dst, const __nv_bfloat16* src) {
    int tid = threadIdx.x;
#pragma unroll
    for (int i = 0; i < 4; i++) {
        int id = tid + i * 256;
        int r = id >> 3, q = id & 7;
        cpa16(dst + r * 144 + q * 16, (const char*)src + (size_t)r * 2048 + q * 16);
    }
}

__global__ __launch_bounds__(256) void proj_kernel(void) {
    extern __shared__ char sm[];
    const u32 sb = smem_u32(sm);
    const int tid = threadIdx.x, w = tid >> 5, lane = tid & 31;
    const int g = lane >> 2, tg = lane & 3;
    const int which = blockIdx.y;
    const int row0 = blockIdx.x * 128;

    const __nv_bfloat16* xh = g_xh + (size_t)row0 * EE;
    const __nv_bfloat16* xl = g_xl + (size_t)row0 * EE;
    const __nv_bfloat16* wth = g_wth[which];
    const __nv_bfloat16* wtl = g_wtl[which];

    float c[16][4];
#pragma unroll
    for (int n = 0; n < 16; n++)
#pragma unroll
        for (int j = 0; j < 4; j++) c[n][j] = 0.0f;

    // prefetch chunk 0
    chunk_load(sb, xh); chunk_load(sb + PJ_T, xl);
    chunk_load(sb + 2*PJ_T, wth); chunk_load(sb + 3*PJ_T, wtl);
    CP_COMMIT();

    for (int ch = 0; ch < 16; ch++) {
        int cur = ch & 1;
        if (ch < 15) {
            u32 nb = sb + (cur ^ 1) * PJ_STG;
            const __nv_bfloat16* xh2 = xh + (ch+1)*64;
            const __nv_bfloat16* xl2 = xl + (ch+1)*64;
            chunk_load(nb, xh2); chunk_load(nb + PJ_T, xl2);
            chunk_load(nb + 2*PJ_T, wth + (ch+1)*64);
            chunk_load(nb + 3*PJ_T, wtl + (ch+1)*64);
            CP_COMMIT();
            CP_WAIT(1);
        } else {
            CP_WAIT(0);
        }
        __syncthreads();
        const char* Xh = sm + cur * PJ_STG;
        const char* Xl = Xh + PJ_T;
        const char* Wh = Xh + 2*PJ_T;
        const char* Wl = Xh + 3*PJ_T;
#pragma unroll
        for (int kt = 0; kt < 4; kt++) {
            u32 ao = (u32)((w*16 + g) * 144 + kt*32 + tg*4);
            u32 ah0 = *(const u32*)(Xh + ao),        ah1 = *(const u32*)(Xh + ao + 8*144);
            u32 ah2 = *(const u32*)(Xh + ao + 16),   ah3 = *(const u32*)(Xh + ao + 16 + 8*144);
            u32 al0 = *(const u32*)(Xl + ao),        al1 = *(const u32*)(Xl + ao + 8*144);
            u32 al2 = *(const u32*)(Xl + ao + 16),   al3 = *(const u32*)(Xl + ao + 16 + 8*144);
#pragma unroll
            for (int n = 0; n < 16; n++) {
                u32 bo = (u32)((n*8 + g) * 144 + kt*32 + tg*4);
                u32 bh0 = *(const u32*)(Wh + bo), bh1 = *(const u32*)(Wh + bo + 16);
                u32 bl0 = *(const u32*)(Wl + bo), bl1 = *(const u32*)(Wl + bo + 16);
                mma16816(c[n], ah0, ah1, ah2, ah3, bh0, bh1);
                mma16816(c[n], ah0, ah1, ah2, ah3, bl0, bl1);
                mma16816(c[n], al0, al1, al2, al3, bh0, bh1);
            }
        }
        __syncthreads();
    }

    if (which < 2) {
        __nv_bfloat16* dh = which ? g_kh : g_qh;
        __nv_bfloat16* dl = which ? g_kl : g_ql;
        size_t rA = (size_t)(row0 + w*16 + g) * HH;
        size_t rB = rA + 8 * HH;
#pragma unroll
        for (int n = 0; n < 16; n++) {
            int col = n*8 + tg*2;
            u32 h0 = packbf(c[n][0], c[n][1]);
            u32 h1 = packbf(c[n][2], c[n][3]);
            *(u32*)&dh[rA + col] = h0;  *(u32*)&dl[rA + col] = packlo(c[n][0], c[n][1], h0);
            *(u32*)&dh[rB + col] = h1;  *(u32*)&dl[rB + col] = packlo(c[n][2], c[n][3], h1);
        }
    } else {
        // stage V f32 in smem, then coalesced transposed store to V^T
        float* Cs = (float*)sm;   // [128][132]
#pragma unroll
        for (int n = 0; n < 16; n++) {
            int col = n*8 + tg*2;
            Cs[(w*16 + g) * 132 + col]     = c[n][0];
            Cs[(w*16 + g) * 132 + col + 1] = c[n][1];
            Cs[(w*16 + g + 8) * 132 + col]     = c[n][2];
            Cs[(w*16 + g + 8) * 132 + col + 1] = c[n][3];
        }
        __syncthreads();
        int h = tid >> 1, half = tid & 1;
        int b = row0 >> 11, s0 = row0 & 2047;
        union { __nv_bfloat16 v[64]; uint4 u[8]; } Hh, Ll;
#pragma unroll
        for (int j = 0; j < 64; j++) {
            float f = Cs[(half*64 + j) * 132 + h];
            __nv_bfloat16 hi = __float2bfloat16_rn(f);
            Hh.v[j] = hi;
            Ll.v[j] = __float2bfloat16_rn(f - __bfloat162float(hi));
        }
        size_t ob = ((size_t)(b*HH + h)) * SS + s0 + half*64;
#pragma unroll
        for (int j = 0; j < 8; j++) {
            *(uint4*)&g_vth[ob + j*8] = Hh.u[j];
            *(uint4*)&g_vtl[ob + j*8] = Ll.u[j];
        }
    }
}

// ---------------------------------------------------------------------------
// attn: CTA = 128 Q rows x one batch. 8 warps, warp = 16 rows.
// S accum in frags; P = frag-relayout (no smem); O accum in frags; l in regs.
// smem: Qh,Ql,Kh,Kl,Vth,Vtl tiles [128][136] bf16 (272B rows).
// Overlap: V(t) load under QK(t); K(t+1) load under softmax+PV(t).
// ---------------------------------------------------------------------------
#define AT_T 34816            // 128*136*2
#define ATT_SMEM (6 * AT_T)

__device__ __forceinline__ void tile_load(u32 dst, const __nv_bfloat16* src,
                                          int stride_elems) {
    int tid = threadIdx.x;
#pragma unroll
    for (int i = 0; i < 8; i++) {
        int id = tid + i * 256;
        int r = id >> 4, q = id & 15;
        cpa16(dst + r * 272 + q * 16,
              (const char*)src + (size_t)r * stride_elems * 2 + q * 16);
    }
}

__global__ __launch_bounds__(256) void attn_kernel(
    const float* __restrict__ du_g, float* __restrict__ out)
{
    extern __shared__ char sm[];
    const u32 sb = smem_u32(sm);
    const int tid = threadIdx.x, w = tid >> 5, lane = tid & 31;
    const int g = lane >> 2, tg = lane & 3;
    const int b = blockIdx.y;
    const int q0 = blockIdx.x * 128;

    const u32 Qh = sb, Ql = sb + AT_T, Kh = sb + 2*AT_T, Kl = sb + 3*AT_T;
    const u32 Vh = sb + 4*AT_T, Vl = sb + 5*AT_T;
    const char *Qhp = sm, *Qlp = sm + AT_T, *Khp = sm + 2*AT_T, *Klp = sm + 3*AT_T;
    const char *Vhp = sm + 4*AT_T, *Vlp = sm + 5*AT_T;

    const size_t qoff = (size_t)(b*SS + q0) * HH;
    tile_load(Qh, g_qh + qoff, HH);
    tile_load(Ql, g_ql + qoff, HH);
    tile_load(Kh, g_kh + (size_t)(b*SS) * HH, HH);
    tile_load(Kl, g_kl + (size_t)(b*SS) * HH, HH);
    CP_COMMIT();

    float o[16][4];
#pragma unroll
    for (int n = 0; n < 16; n++)
#pragma unroll
        for (int j = 0; j < 4; j++) o[n][j] = 0.0f;
    float lsumA = 0.0f, lsumB = 0.0f;

    const float SC = 0.03125f;        // 1024^-0.5
    const float INVK = 1.0f / 0.9f;
    const float* duA = du_g + ((size_t)(b*SS) + q0 + w*16 + g) * SS;
    const float* duB = duA + 8 * SS;

    CP_WAIT(0);
    __syncthreads();

    for (int t = 0; t < 16; t++) {
        const int k0 = t * 128;
        // V(t) load overlaps QK(t)
        tile_load(Vh, g_vth + (size_t)(b*HH) * SS + k0, SS);
        tile_load(Vl, g_vtl + (size_t)(b*HH) * SS + k0, SS);
        CP_COMMIT();

        float c[16][4];
#pragma unroll
        for (int n = 0; n < 16; n++)
#pragma unroll
            for (int j = 0; j < 4; j++) c[n][j] = 0.0f;

#pragma unroll
        for (int kt = 0; kt < 8; kt++) {
            u32 ao = (u32)((w*16 + g) * 272 + kt*32 + tg*4);
            u32 ah0 = *(const u32*)(Qhp + ao),      ah1 = *(const u32*)(Qhp + ao + 8*272);
            u32 ah2 = *(const u32*)(Qhp + ao + 16), ah3 = *(const u32*)(Qhp + ao + 16 + 8*272);
            u32 al0 = *(const u32*)(Qlp + ao),      al1 = *(const u32*)(Qlp + ao + 8*272);
            u32 al2 = *(const u32*)(Qlp + ao + 16), al3 = *(const u32*)(Qlp + ao + 16 + 8*272);
#pragma unroll
            for (int n = 0; n < 16; n++) {
                u32 bo = (u32)((n*8 + g) * 272 + kt*32 + tg*4);
                u32 bh0 = *(const u32*)(Khp + bo), bh1 = *(const u32*)(Khp + bo + 16);
                u32 bl0 = *(const u32*)(Klp + bo), bl1 = *(const u32*)(Klp + bo + 16);
                mma16816(c[n], ah0, ah1, ah2, ah3, bh0, bh1);
                mma16816(c[n], ah0, ah1, ah2, ah3, bl0, bl1);
                mma16816(c[n], al0, al1, al2, al3, bh0, bh1);
            }
        }

        CP_WAIT(0);          // V(t) ready
        __syncthreads();     // all warps done with K(t) -> K buffer reusable
        if (t < 15) {
            tile_load(Kh, g_kh + (size_t)(b*SS + k0 + 128) * HH, HH);
            tile_load(Kl, g_kl + (size_t)(b*SS + k0 + 128) * HH, HH);
            CP_COMMIT();
        }

        // softmax + dropout + PV, per k-tile (frag relayout: S C-frag == P A-frag)
#pragma unroll
        for (int kt = 0; kt < 8; kt++) {
            u32 ph[4], pl[4];
#pragma unroll
            for (int half = 0; half < 2; half++) {
                int n = 2*kt + half;
                float p0 = __expf(c[n][0] * SC), p1 = __expf(c[n][1] * SC);
                float p2 = __expf(c[n][2] * SC), p3 = __expf(c[n][3] * SC);
                lsumA += p0 + p1;
                lsumB += p2 + p3;
                float2 dA = *(const float2*)(duA + k0 + n*8 + tg*2);
                float2 dB = *(const float2*)(duB + k0 + n*8 + tg*2);
                p0 *= (dA.x >= 0.1f) ? INVK : 0.0f;
                p1 *= (dA.y >= 0.1f) ? INVK : 0.0f;
                p2 *= (dB.x >= 0.1f) ? INVK : 0.0f;
                p3 *= (dB.y >= 0.1f) ? INVK : 0.0f;
                ph[2*half]     = packbf(p0, p1);
                pl[2*half]     = packlo(p0, p1, ph[2*half]);
                ph[2*half + 1] = packbf(p2, p3);
                pl[2*half + 1] = packlo(p2, p3, ph[2*half + 1]);
            }
            // A-frag order: a0=ph[0](row g,k lo), a1=ph[1](row g+8), a2=ph[2], a3=ph[3]
#pragma unroll
            for (int n = 0; n < 16; n++) {
                u32 bo = (u32)((n*8 + g) * 272 + kt*32 + tg*4);
                u32 bh0 = *(const u32*)(Vhp + bo), bh1 = *(const u32*)(Vhp + bo + 16);
                u32 bl0 = *(const u32*)(Vlp + bo), bl1 = *(const u32*)(Vlp + bo + 16);
                mma16816(o[n], ph[0], ph[1], ph[2], ph[3], bh0, bh1);
                mma16816(o[n], ph[0], ph[1], ph[2], ph[3], bl0, bl1);
                mma16816(o[n], pl[0], pl[1], pl[2], pl[3], bh0, bh1);
            }
        }
        if (t < 15) CP_WAIT(0);   // K(t+1) ready
        __syncthreads();          // V buffer reuse safety
    }

    // full row sums: reduce over the 4 quad lanes
#pragma unroll
    for (int off = 1; off <= 2; off <<= 1) {
        lsumA += __shfl_xor_sync(0xffffffffu, lsumA, off);
        lsumB += __shfl_xor_sync(0xffffffffu, lsumB, off);
    }
    const float invA = 1.0f / lsumA, invB = 1.0f / lsumB;

    float* oA = out + ((size_t)(b*SS) + q0 + w*16 + g) * HH;
    float* oB = oA + 8 * HH;
#pragma unroll
    for (int n = 0; n < 16; n++) {
        int col = n*8 + tg*2;
        *(float2*)(oA + col) = make_float2(o[n][0] * invA, o[n][1] * invA);
        *(float2*)(oB + col) = make_float2(o[n][2] * invB, o[n][3] * invB);
    }
}

extern "C" void kernel_launch(void* const* d_in, const int* in_sizes, int n_in,
                              void* d_out, int out_size)
{
    const float* x  = (const float*)d_in[0];
    const float* wq = (const float*)d_in[1];
    const float* wk = (const float*)d_in[2];
    const float* wv = (const float*)d_in[3];
    const float* du = (const float*)d_in[4];
    float* out = (float*)d_out;

    cudaFuncSetAttribute(proj_kernel, cudaFuncAttributeMaxDynamicSharedMemorySize, PROJ_SMEM);
    cudaFuncSetAttribute(attn_kernel, cudaFuncAttributeMaxDynamicSharedMemorySize, ATT_SMEM);

    xprep_kernel<<<(BB*SS*EE/4 + 255) / 256, 256>>>(x);
    wprep_kernel<<<EE*HH / 256, 256>>>(wq, wk, wv);
    dim3 g1(BB*SS / 128, 3);
    proj_kernel<<<g1, 256, PROJ_SMEM>>>();
    dim3 g2(SS / 128, BB);
    attn_kernel<<<g2, 256, ATT_SMEM>>>(du, out);
}

// round 8
// speedup vs baseline: 4.6318x; 1.1531x over previous
#include <cuda_runtime.h>
#include <cuda_bf16.h>

#define BB 8
#define SS 2048
#define EE 1024
#define HH 128

typedef unsigned int u32;

// ---------------- device scratch ----------------
__device__ __nv_bfloat16 g_xh[BB*SS*EE], g_xl[BB*SS*EE];     // X split [s][e]
__device__ __nv_bfloat16 g_wth[3][HH*EE], g_wtl[3][HH*EE];   // W^T split [h][e]
__device__ __nv_bfloat16 g_qh[BB*SS*HH], g_ql[BB*SS*HH];     // Q [s][h]
__device__ __nv_bfloat16 g_kh[BB*SS*HH];                     // K hi [s][h]
__device__ __nv_bfloat16 g_vth[BB*HH*SS], g_vtl[BB*HH*SS];   // V^T [b][h][s]
__device__ u32 g_mask[BB*SS*SS/32];                          // dropout keep bits

// ---------------- helpers ----------------
__device__ __forceinline__ u32 smem_u32(const void* p) {
    u32 a;
    asm("{ .reg .u64 t; cvta.to.shared.u64 t, %1; cvt.u32.u64 %0, t; }" : "=r"(a) : "l"(p));
    return a;
}
__device__ __forceinline__ void cpa16(u32 dst, const void* src) {
    asm volatile("cp.async.cg.shared.global [%0], [%1], 16;" :: "r"(dst), "l"(src));
}
#define CP_COMMIT() asm volatile("cp.async.commit_group;" ::: "memory")
#define CP_WAIT(n)  asm volatile("cp.async.wait_group %0;" :: "n"(n) : "memory")

__device__ __forceinline__ u32 packbf(float lo, float hi) {
    u32 r;
    asm("cvt.rn.bf16x2.f32 %0, %1, %2;" : "=r"(r) : "f"(hi), "f"(lo));
    return r;
}
__device__ __forceinline__ u32 packlo(float p0, float p1, u32 h) {
    float r0 = p0 - __uint_as_float(h << 16);
    float r1 = p1 - __uint_as_float(h & 0xffff0000u);
    return packbf(r0, r1);
}
__device__ __forceinline__ void mma16816(float* c, u32 a0, u32 a1, u32 a2, u32 a3,
                                         u32 b0, u32 b1) {
    asm volatile("mma.sync.aligned.m16n8k16.row.col.f32.bf16.bf16.f32 "
                 "{%0,%1,%2,%3},{%4,%5,%6,%7},{%8,%9},{%0,%1,%2,%3};"
                 : "+f"(c[0]), "+f"(c[1]), "+f"(c[2]), "+f"(c[3])
                 : "r"(a0), "r"(a1), "r"(a2), "r"(a3), "r"(b0), "r"(b1));
}
__device__ __forceinline__ void mmaA(float* c, const uint4& a, u32 b0, u32 b1) {
    mma16816(c, a.x, a.y, a.z, a.w, b0, b1);
}
__device__ __forceinline__ uint4 ldm4(u32 addr) {
    uint4 r;
    asm volatile("ldmatrix.sync.aligned.m8n8.x4.shared.b16 {%0,%1,%2,%3}, [%4];"
                 : "=r"(r.x), "=r"(r.y), "=r"(r.z), "=r"(r.w) : "r"(addr));
    return r;
}

// ---------------------------------------------------------------------------
// prep kernels
// ---------------------------------------------------------------------------
__global__ __launch_bounds__(256) void xprep_kernel(const float* __restrict__ x) {
    size_t i = ((size_t)blockIdx.x * 256 + threadIdx.x) * 4;
    float4 v = *(const float4*)(x + i);
    u32 h01 = packbf(v.x, v.y), h23 = packbf(v.z, v.w);
    u32 l01 = packlo(v.x, v.y, h01), l23 = packlo(v.z, v.w, h23);
    *(uint2*)&g_xh[i] = make_uint2(h01, h23);
    *(uint2*)&g_xl[i] = make_uint2(l01, l23);
}
__global__ __launch_bounds__(256) void wprep_kernel(
    const float* __restrict__ wq, const float* __restrict__ wk,
    const float* __restrict__ wv)
{
    int idx = blockIdx.x * 256 + threadIdx.x;   // e*128+h
    int e = idx >> 7, h = idx & 127;
    int o = h * EE + e;
    const float* src[3] = {wq, wk, wv};
#pragma unroll
    for (int m = 0; m < 3; m++) {
        float v = src[m][idx];
        __nv_bfloat16 hi = __float2bfloat16_rn(v);
        g_wth[m][o] = hi;
        g_wtl[m][o] = __float2bfloat16_rn(v - __bfloat162float(hi));
    }
}
__global__ __launch_bounds__(256) void maskprep_kernel(const float* __restrict__ du) {
    size_t gid = (size_t)blockIdx.x * 256 + threadIdx.x;
    u32 m = __ballot_sync(0xffffffffu, du[gid] >= 0.1f);
    if ((threadIdx.x & 31) == 0) g_mask[gid >> 5] = m;
}

// ---------------------------------------------------------------------------
// proj: C[128 x 128] = X @ W (q/k/v by blockIdx.y). q/k: 2-pass (Xh*Wh + Xh*Wl);
// v: 3-pass (+ Xl*Wh). ldmatrix frags, pass-major for ILP, cp.async 2-stage.
// smem tile: [128][72] bf16 (144B pitch).
// ---------------------------------------------------------------------------
#define PJ_T 18432            // 128*72*2
#define PJ_STG (4 * PJ_T)     // Xh,Xl,Wh,Wl slots
#define PROJ_SMEM (2 * PJ_STG)

__device__ __forceinline__ void chunk_load(u32 dst, const __nv_bfloat16* src) {
    int tid = threadIdx.x;
#pragma unroll
    for (int i = 0; i < 4; i++) {
        int id = tid + i * 256;
        int r = id >> 3, q = id & 7;
        cpa16(dst + r * 144 + q * 16, (const char*)src + (size_t)r * 2048 + q * 16);
    }
}

__global__ __launch_bounds__(256) void proj_kernel(void) {
    extern __shared__ char sm[];
    const u32 sb = smem_u32(sm);
    const int tid = threadIdx.x, w = tid >> 5, lane = tid & 31;
    const int g = lane >> 2, tg = lane & 3;
    const int which = blockIdx.y;
    const int row0 = blockIdx.x * 128;
    const bool isv = (which == 2);

    const __nv_bfloat16* xh = g_xh + (size_t)row0 * EE;
    const __nv_bfloat16* xl = g_xl + (size_t)row0 * EE;
    const __nv_bfloat16* wth = g_wth[which];
    const __nv_bfloat16* wtl = g_wtl[which];

    // ldmatrix per-lane offsets
    const u32 aoff = (u32)((w*16 + (lane & 15)) * 144 + ((lane >> 4) & 1) * 16);
    const u32 boff = (u32)(((lane & 7) + ((lane >> 4) & 1) * 8) * 144 + ((lane >> 3) & 1) * 16);

    float c[16][4];
#pragma unroll
    for (int n = 0; n < 16; n++)
#pragma unroll
        for (int j = 0; j < 4; j++) c[n][j] = 0.0f;

    chunk_load(sb, xh);
    if (isv) chunk_load(sb + PJ_T, xl);
    chunk_load(sb + 2*PJ_T, wth);
    chunk_load(sb + 3*PJ_T, wtl);
    CP_COMMIT();

    for (int ch = 0; ch < 16; ch++) {
        int cur = ch & 1;
        if (ch < 15) {
            u32 nb = sb + (cur ^ 1) * PJ_STG;
            chunk_load(nb, xh + (ch+1)*64);
            if (isv) chunk_load(nb + PJ_T, xl + (ch+1)*64);
            chunk_load(nb + 2*PJ_T, wth + (ch+1)*64);
            chunk_load(nb + 3*PJ_T, wtl + (ch+1)*64);
            CP_COMMIT();
            CP_WAIT(1);
        } else {
            CP_WAIT(0);
        }
        __syncthreads();
        const u32 Xh = sb + cur * PJ_STG;
        const u32 Xl = Xh + PJ_T;
        const u32 Wh = Xh + 2*PJ_T;
        const u32 Wl = Xh + 3*PJ_T;
#pragma unroll
        for (int kt = 0; kt < 4; kt++) {
            uint4 AH = ldm4(Xh + aoff + kt*32);
            // pass 1: Xh * Wh
#pragma unroll
            for (int np = 0; np < 8; np++) {
                uint4 B = ldm4(Wh + boff + np*2304 + kt*32);
                mmaA(c[2*np], AH, B.x, B.y);
                mmaA(c[2*np+1], AH, B.z, B.w);
            }
            // pass 2: Xh * Wl
#pragma unroll
            for (int np = 0; np < 8; np++) {
                uint4 B = ldm4(Wl + boff + np*2304 + kt*32);
                mmaA(c[2*np], AH, B.x, B.y);
                mmaA(c[2*np+1], AH, B.z, B.w);
            }
            if (isv) {   // pass 3: Xl * Wh
                uint4 AL = ldm4(Xl + aoff + kt*32);
#pragma unroll
                for (int np = 0; np < 8; np++) {
                    uint4 B = ldm4(Wh + boff + np*2304 + kt*32);
                    mmaA(c[2*np], AL, B.x, B.y);
                    mmaA(c[2*np+1], AL, B.z, B.w);
                }
            }
        }
        __syncthreads();
    }

    if (which < 2) {
        __nv_bfloat16* dh = which ? g_kh : g_qh;
        size_t rA = (size_t)(row0 + w*16 + g) * HH;
        size_t rB = rA + 8 * HH;
#pragma unroll
        for (int n = 0; n < 16; n++) {
            int col = n*8 + tg*2;
            u32 h0 = packbf(c[n][0], c[n][1]);
            u32 h1 = packbf(c[n][2], c[n][3]);
            *(u32*)&dh[rA + col] = h0;
            *(u32*)&dh[rB + col] = h1;
            if (which == 0) {
                *(u32*)&g_ql[rA + col] = packlo(c[n][0], c[n][1], h0);
                *(u32*)&g_ql[rB + col] = packlo(c[n][2], c[n][3], h1);
            }
        }
    } else {
        float* Cs = (float*)sm;   // [128][132]
#pragma unroll
        for (int n = 0; n < 16; n++) {
            int col = n*8 + tg*2;
            Cs[(w*16 + g) * 132 + col]     = c[n][0];
            Cs[(w*16 + g) * 132 + col + 1] = c[n][1];
            Cs[(w*16 + g + 8) * 132 + col]     = c[n][2];
            Cs[(w*16 + g + 8) * 132 + col + 1] = c[n][3];
        }
        __syncthreads();
        int h = tid >> 1, half = tid & 1;
        int b = row0 >> 11, s0 = row0 & 2047;
        union { __nv_bfloat16 v[64]; uint4 u[8]; } Hh, Ll;
#pragma unroll
        for (int j = 0; j < 64; j++) {
            float f = Cs[(half*64 + j) * 132 + h];
            __nv_bfloat16 hi = __float2bfloat16_rn(f);
            Hh.v[j] = hi;
            Ll.v[j] = __float2bfloat16_rn(f - __bfloat162float(hi));
        }
        size_t ob = ((size_t)(b*HH + h)) * SS + s0 + half*64;
#pragma unroll
        for (int j = 0; j < 8; j++) {
            *(uint4*)&g_vth[ob + j*8] = Hh.u[j];
            *(uint4*)&g_vtl[ob + j*8] = Ll.u[j];
        }
    }
}

// ---------------------------------------------------------------------------
// attn: CTA = 128 Q rows x one batch. 8 warps, warp = 16 rows.
// QK 2-pass (Qh*Kh + Ql*Kh); PV 3-pass. Pass-major + ldmatrix. Dropout via
// prepacked bitmask. smem: Qh,Ql,Kh,Vth,Vtl [128][136] bf16 (272B pitch).
// ---------------------------------------------------------------------------
#define AT_T 34816            // 128*136*2
#define ATT_SMEM (5 * AT_T)

__device__ __forceinline__ void tile_load(u32 dst, const __nv_bfloat16* src,
                                          int stride_elems) {
    int tid = threadIdx.x;
#pragma unroll
    for (int i = 0; i < 8; i++) {
        int id = tid + i * 256;
        int r = id >> 4, q = id & 15;
        cpa16(dst + r * 272 + q * 16,
              (const char*)src + (size_t)r * stride_elems * 2 + q * 16);
    }
}

__global__ __launch_bounds__(256) void attn_kernel(float* __restrict__ out)
{
    extern __shared__ char sm[];
    const u32 sb = smem_u32(sm);
    const int tid = threadIdx.x, w = tid >> 5, lane = tid & 31;
    const int g = lane >> 2, tg = lane & 3;
    const int b = blockIdx.y;
    const int q0 = blockIdx.x * 128;

    const u32 Qh = sb, Ql = sb + AT_T, Kh = sb + 2*AT_T;
    const u32 Vh = sb + 3*AT_T, Vl = sb + 4*AT_T;

    const u32 aoff = (u32)((w*16 + (lane & 15)) * 272 + ((lane >> 4) & 1) * 16);
    const u32 boff = (u32)(((lane & 7) + ((lane >> 4) & 1) * 8) * 272 + ((lane >> 3) & 1) * 16);

    const size_t qoff = (size_t)(b*SS + q0) * HH;
    tile_load(Qh, g_qh + qoff, HH);
    tile_load(Ql, g_ql + qoff, HH);
    tile_load(Kh, g_kh + (size_t)(b*SS) * HH, HH);
    CP_COMMIT();

    float o[16][4];
#pragma unroll
    for (int n = 0; n < 16; n++)
#pragma unroll
        for (int j = 0; j < 4; j++) o[n][j] = 0.0f;
    float lsumA = 0.0f, lsumB = 0.0f;

    const float SC = 0.03125f;        // 1024^-0.5
    const float INVK = 1.0f / 0.9f;
    const u32* mrowA = g_mask + ((size_t)(b*SS) + q0 + w*16 + g) * (SS/32);
    const u32* mrowB = mrowA + 8 * (SS/32);

    CP_WAIT(0);
    __syncthreads();

    for (int t = 0; t < 16; t++) {
        const int k0 = t * 128;
        // V(t) load overlaps QK(t)
        tile_load(Vh, g_vth + (size_t)(b*HH) * SS + k0, SS);
        tile_load(Vl, g_vtl + (size_t)(b*HH) * SS + k0, SS);
        CP_COMMIT();
        // dropout mask words for this tile (latency covered by QK MMAs)
        uint4 mA = *(const uint4*)(mrowA + t*4);
        uint4 mB = *(const uint4*)(mrowB + t*4);

        float c[16][4];
#pragma unroll
        for (int n = 0; n < 16; n++)
#pragma unroll
            for (int j = 0; j < 4; j++) c[n][j] = 0.0f;

#pragma unroll
        for (int kt = 0; kt < 8; kt++) {
            uint4 AH = ldm4(Qh + aoff + kt*32);
            uint4 AL = ldm4(Ql + aoff + kt*32);
            // pass 1: Qh * Kh
#pragma unroll
            for (int np = 0; np < 8; np++) {
                uint4 B = ldm4(Kh + boff + np*4352 + kt*32);
                mmaA(c[2*np], AH, B.x, B.y);
                mmaA(c[2*np+1], AH, B.z, B.w);
            }
            // pass 2: Ql * Kh
#pragma unroll
            for (int np = 0; np < 8; np++) {
                uint4 B = ldm4(Kh + boff + np*4352 + kt*32);
                mmaA(c[2*np], AL, B.x, B.y);
                mmaA(c[2*np+1], AL, B.z, B.w);
            }
        }

        CP_WAIT(0);          // V(t) ready
        __syncthreads();     // all warps done reading K(t)
        if (t < 15) {
            tile_load(Kh, g_kh + (size_t)(b*SS + k0 + 128) * HH, HH);
            CP_COMMIT();
        }

        // softmax + dropout(numerator only) + PV
#pragma unroll
        for (int kt = 0; kt < 8; kt++) {
            u32 ph[4], pl[4];
            u32 wa = ((const u32*)&mA)[kt >> 1];
            u32 wb = ((const u32*)&mB)[kt >> 1];
#pragma unroll
            for (int half = 0; half < 2; half++) {
                int n = 2*kt + half;
                int sh = (kt & 1)*16 + half*8 + tg*2;
                float p0 = __expf(c[n][0] * SC), p1 = __expf(c[n][1] * SC);
                float p2 = __expf(c[n][2] * SC), p3 = __expf(c[n][3] * SC);
                lsumA += p0 + p1;
                lsumB += p2 + p3;
                p0 *= ((wa >> sh) & 1)     ? INVK : 0.0f;
                p1 *= ((wa >> (sh+1)) & 1) ? INVK : 0.0f;
                p2 *= ((wb >> sh) & 1)     ? INVK : 0.0f;
                p3 *= ((wb >> (sh+1)) & 1) ? INVK : 0.0f;
                ph[2*half]     = packbf(p0, p1);
                pl[2*half]     = packlo(p0, p1, ph[2*half]);
                ph[2*half + 1] = packbf(p2, p3);
                pl[2*half + 1] = packlo(p2, p3, ph[2*half + 1]);
            }
            // pass 1: Ph * Vh
#pragma unroll
            for (int np = 0; np < 8; np++) {
                uint4 B = ldm4(Vh + boff + np*4352 + kt*32);
                mma16816(o[2*np], ph[0], ph[1], ph[2], ph[3], B.x, B.y);
                mma16816(o[2*np+1], ph[0], ph[1], ph[2], ph[3], B.z, B.w);
            }
            // pass 2: Ph * Vl
#pragma unroll
            for (int np = 0; np < 8; np++) {
                uint4 B = ldm4(Vl + boff + np*4352 + kt*32);
                mma16816(o[2*np], ph[0], ph[1], ph[2], ph[3], B.x, B.y);
                mma16816(o[2*np+1], ph[0], ph[1], ph[2], ph[3], B.z, B.w);
            }
            // pass 3: Pl * Vh
#pragma unroll
            for (int np = 0; np < 8; np++) {
                uint4 B = ldm4(Vh + boff + np*4352 + kt*32);
                mma16816(o[2*np], pl[0], pl[1], pl[2], pl[3], B.x, B.y);
                mma16816(o[2*np+1], pl[0], pl[1], pl[2], pl[3], B.z, B.w);
            }
        }
        if (t < 15) CP_WAIT(0);   // K(t+1) ready
        __syncthreads();          // V buffer reuse safety
    }

    // per-row softmax denominators: reduce over quad lanes
#pragma unroll
    for (int off = 1; off <= 2; off <<= 1) {
        lsumA += __shfl_xor_sync(0xffffffffu, lsumA, off);
        lsumB += __shfl_xor_sync(0xffffffffu, lsumB, off);
    }
    const float invA = 1.0f / lsumA, invB = 1.0f / lsumB;

    float* oA = out + ((size_t)(b*SS) + q0 + w*16 + g) * HH;
    float* oB = oA + 8 * HH;
#pragma unroll
    for (int n = 0; n < 16; n++) {
        int col = n*8 + tg*2;
        *(float2*)(oA + col) = make_float2(o[n][0] * invA, o[n][1] * invA);
        *(float2*)(oB + col) = make_float2(o[n][2] * invB, o[n][3] * invB);
    }
}

extern "C" void kernel_launch(void* const* d_in, const int* in_sizes, int n_in,
                              void* d_out, int out_size)
{
    const float* x  = (const float*)d_in[0];
    const float* wq = (const float*)d_in[1];
    const float* wk = (const float*)d_in[2];
    const float* wv = (const float*)d_in[3];
    const float* du = (const float*)d_in[4];
    float* out = (float*)d_out;

    cudaFuncSetAttribute(proj_kernel, cudaFuncAttributeMaxDynamicSharedMemorySize, PROJ_SMEM);
    cudaFuncSetAttribute(attn_kernel, cudaFuncAttributeMaxDynamicSharedMemorySize, ATT_SMEM);

    xprep_kernel<<<(BB*SS*EE/4 + 255) / 256, 256>>>(x);
    wprep_kernel<<<EE*HH / 256, 256>>>(wq, wk, wv);
    maskprep_kernel<<<(int)((size_t)BB*SS*SS / 256), 256>>>(du);
    dim3 g1(BB*SS / 128, 3);
    proj_kernel<<<g1, 256, PROJ_SMEM>>>();
    dim3 g2(SS / 128, BB);
    attn_kernel<<<g2, 256, ATT_SMEM>>>(out);
}